// round 9
// baseline (speedup 1.0000x reference)
#include <cuda_runtime.h>

#define N 512
#define KC 16          // k-chunk
#define NCHUNK (N / KC)
#define NTILE 16       // 512/32 tile grid
#define NBLK (NTILE * (NTILE + 1) / 2)   // 136 upper-triangle blocks (one wave)
#define PAD 36         // SMEM row stride in floats: 144B keeps LDS.128 16B-aligned
#define NT 128         // threads per block

// Scratch (no allocations allowed).
__device__ float d_sim[N * N];
__device__ float d_acc;
__device__ unsigned d_done;   // ticket, wraps mod NBLK each replay
__device__ unsigned d_bar;    // monotonic grid-barrier counter (never reset)

// sigmoid(diff/0.01): sigmoid(x) = 0.5 + 0.5*tanh(x/2); tanh.approx saturates
// exactly where the reference's clipped sigmoid is 0/1, so the clip is free.
__device__ __forceinline__ float sig100(float diff) {
    float t;
    asm("tanh.approx.f32 %0, %1;" : "=f"(t) : "f"(50.0f * diff));
    return fmaf(0.5f, t, 0.5f);
}

// Single persistent kernel: Phase 1 symmetric SGEMM -> grid barrier ->
// Phase 2 positives-only SmoothAP with pipelined row prefetch.
__global__ __launch_bounds__(NT) void fused_kernel(const float* __restrict__ P,
                                                   const int* __restrict__ labels,
                                                   float* __restrict__ out) {
    __shared__ float As[2][KC][PAD];
    __shared__ float Bs[2][KC][PAD];
    __shared__ float Ct[32][33];
    __shared__ float srow[2][N];   // double-buffered sim rows
    __shared__ float pflag[N];
    __shared__ int   slab[N];      // labels cache
    __shared__ int   jlist[N];
    __shared__ int   cnt;
    __shared__ float ssum;

    const int b = blockIdx.x;
    const int tid = threadIdx.x;

    if (b == 0 && tid == 0) d_acc = 0.0f;   // pre-barrier: ordered vs all adds

    // ================= Phase 1: GEMM sim = P*P^T (upper-triangle tiles) ====
    {
        int bi = 0, rem = b;
        #pragma unroll
        for (int r = 0; r < NTILE; r++) {
            int c = NTILE - r;
            if (rem >= c) { rem -= c; bi++; } else break;
        }
        const int bj = bi + rem;
        const int row0 = bi * 32, col0 = bj * 32;

        const int tx = tid & 15;          // col pair
        const int ty = tid >> 4;          // row quad
        const int lrow = tid >> 2;        // load row 0..31
        const int lk = (tid & 3) * 4;     // load k offset

        float acc[4][2];
        #pragma unroll
        for (int m = 0; m < 4; m++) { acc[m][0] = 0.f; acc[m][1] = 0.f; }

        float4 ra = *reinterpret_cast<const float4*>(&P[(row0 + lrow) * N + lk]);
        float4 rb = *reinterpret_cast<const float4*>(&P[(col0 + lrow) * N + lk]);
        As[0][lk + 0][lrow] = ra.x; As[0][lk + 1][lrow] = ra.y;
        As[0][lk + 2][lrow] = ra.z; As[0][lk + 3][lrow] = ra.w;
        Bs[0][lk + 0][lrow] = rb.x; Bs[0][lk + 1][lrow] = rb.y;
        Bs[0][lk + 2][lrow] = rb.z; Bs[0][lk + 3][lrow] = rb.w;
        __syncthreads();

        for (int c = 0; c < NCHUNK; c++) {
            const int cur = c & 1;
            if (c + 1 < NCHUNK) {
                const int k0 = (c + 1) * KC;
                ra = *reinterpret_cast<const float4*>(&P[(row0 + lrow) * N + k0 + lk]);
                rb = *reinterpret_cast<const float4*>(&P[(col0 + lrow) * N + k0 + lk]);
            }
            #pragma unroll
            for (int kk = 0; kk < KC; kk++) {
                const float4 a = *reinterpret_cast<const float4*>(&As[cur][kk][ty * 4]);
                const float2 bb = *reinterpret_cast<const float2*>(&Bs[cur][kk][tx * 2]);
                acc[0][0] = fmaf(a.x, bb.x, acc[0][0]); acc[0][1] = fmaf(a.x, bb.y, acc[0][1]);
                acc[1][0] = fmaf(a.y, bb.x, acc[1][0]); acc[1][1] = fmaf(a.y, bb.y, acc[1][1]);
                acc[2][0] = fmaf(a.z, bb.x, acc[2][0]); acc[2][1] = fmaf(a.z, bb.y, acc[2][1]);
                acc[3][0] = fmaf(a.w, bb.x, acc[3][0]); acc[3][1] = fmaf(a.w, bb.y, acc[3][1]);
            }
            if (c + 1 < NCHUNK) {
                const int nxt = cur ^ 1;
                As[nxt][lk + 0][lrow] = ra.x; As[nxt][lk + 1][lrow] = ra.y;
                As[nxt][lk + 2][lrow] = ra.z; As[nxt][lk + 3][lrow] = ra.w;
                Bs[nxt][lk + 0][lrow] = rb.x; Bs[nxt][lk + 1][lrow] = rb.y;
                Bs[nxt][lk + 2][lrow] = rb.z; Bs[nxt][lk + 3][lrow] = rb.w;
            }
            __syncthreads();
        }

        #pragma unroll
        for (int m = 0; m < 4; m++) {
            float2 v = make_float2(acc[m][0], acc[m][1]);
            *reinterpret_cast<float2*>(&d_sim[(row0 + ty * 4 + m) * N + col0 + tx * 2]) = v;
        }
        if (bi != bj) {
            #pragma unroll
            for (int m = 0; m < 4; m++) {
                Ct[tx * 2 + 0][ty * 4 + m] = acc[m][0];
                Ct[tx * 2 + 1][ty * 4 + m] = acc[m][1];
            }
            __syncthreads();
            #pragma unroll
            for (int idx = tid; idx < 1024; idx += NT) {
                const int r2 = idx >> 5, c2 = idx & 31;
                d_sim[(col0 + r2) * N + row0 + c2] = Ct[r2][c2];
            }
        }
    }

    // ================= Grid barrier (all 136 blocks resident: one wave) ====
    __threadfence();
    __syncthreads();
    if (tid == 0) {
        const unsigned old = atomicAdd(&d_bar, 1u);
        const unsigned target = (old / NBLK + 1u) * NBLK;
        while (*(volatile unsigned*)&d_bar < target) { }
        __threadfence();
    }
    __syncthreads();

    // ================= Phase 2: SmoothAP, positives-only ===================
    // Block b handles anchors b, b+136, b+272 (, b+408 if b<104).
    const int na = (b < 512 - 3 * NBLK ? 4 : 3);   // 512 = 3*136 + 104
    const int lane = tid & 31, w = tid >> 5;

    for (int k = tid; k < N; k += NT) slab[k] = labels[k];
    {   // preload first row
        float4 v = *reinterpret_cast<const float4*>(&d_sim[b * N + tid * 4]);
        *reinterpret_cast<float4*>(&srow[0][tid * 4]) = v;
    }

    float block_acc = 0.0f;

    for (int a = 0; a < na; a++) {
        const int cur = a & 1;
        const int i = b + a * NBLK;

        float4 pfn;
        if (a + 1 < na)
            pfn = *reinterpret_cast<const float4*>(&d_sim[(b + (a + 1) * NBLK) * N + tid * 4]);

        if (tid == 0) { cnt = 1; ssum = 0.0f; jlist[0] = i; }
        __syncthreads();   // slab/srow[cur] ready; cnt reset visible

        const int li = slab[i];
        for (int k = tid; k < N; k += NT) {
            const bool p = (slab[k] == li) && (k != i);
            pflag[k] = p ? 1.0f : 0.0f;
            if (p) jlist[atomicAdd(&cnt, 1)] = k;
        }
        __syncthreads();
        const int m1 = cnt;            // n_pos = m + 1

        for (int jj = w; jj < m1; jj += NT / 32) {
            const int j = jlist[jj];
            const float sj = srow[cur][j];
            float sa = 0.0f, sp = 0.0f;
            #pragma unroll
            for (int it = 0; it < N / 32; it++) {
                const int k = lane + it * 32;
                float g = sig100(srow[cur][k] - sj);
                g = (k == j) ? 0.0f : g;           // (1-eye)[j,k]
                sa += g;
                sp = fmaf(g, pflag[k], sp);
            }
            #pragma unroll
            for (int o = 16; o; o >>= 1) {
                sa += __shfl_xor_sync(0xFFFFFFFFu, sa, o);
                sp += __shfl_xor_sync(0xFFFFFFFFu, sp, o);
            }
            if (lane == 0) {
                const float ratio = (jj == 0) ? 1.0f / (1.0f + sa)
                                              : (1.0f + sp) / (1.0f + sa);
                atomicAdd(&ssum, ratio);
            }
        }
        __syncthreads();               // jobs done: ssum final, srow[cur] free

        if (tid == 0 && m1 > 1) block_acc += ssum / (float)m1;
        if (a + 1 < na)
            *reinterpret_cast<float4*>(&srow[cur ^ 1][tid * 4]) = pfn;
        // next iteration's first __syncthreads orders srow[nxt] for all
    }

    if (tid == 0) {
        atomicAdd(&d_acc, block_acc);
        __threadfence();
        const unsigned old = atomicInc(&d_done, NBLK - 1);   // wraps to 0
        if (old == NBLK - 1)
            out[0] = 1.0f - atomicAdd(&d_acc, 0.0f) / (float)N;
    }
}

extern "C" void kernel_launch(void* const* d_in, const int* in_sizes, int n_in,
                              void* d_out, int out_size) {
    const float* preds = (const float*)d_in[0];
    const int* labels = (const int*)d_in[1];
    float* out = (float*)d_out;

    fused_kernel<<<NBLK, NT>>>(preds, labels, out);
}